// round 4
// baseline (speedup 1.0000x reference)
#include <cuda_runtime.h>
#include <cuda_bf16.h>
#include <cstdint>

// Problem constants (fixed by the dataset)
#define BATCH   4
#define NNODES  50000
#define NEDGES  800000
#define FIN     128
#define FOUT    128
#define MROWS   (BATCH * NNODES)          // 200000 GEMM rows
#define NBSTRIDE ((size_t)NNODES * FOUT)  // per-batch stride in h/out

// ---------------- device scratch (no cudaMalloc allowed) ----------------
__device__ float          g_h[(size_t)BATCH * NNODES * FOUT]; // 102.4 MB
__device__ __nv_bfloat16  g_Wh[FOUT * FIN];
__device__ __nv_bfloat16  g_Wl[FOUT * FIN];
__device__ int            g_cnt[NNODES];
__device__ int            g_rowptr[NNODES + 1];
__device__ int            g_wofs[NNODES];
__device__ int            g_scol[NEDGES];
__device__ float          g_sval[NEDGES];

// ---------------- W split: W = Wh + Wl (bf16 pair) ----------------
__global__ void wsplit_kernel(const float* __restrict__ W) {
    int i = blockIdx.x * blockDim.x + threadIdx.x;
    if (i < FOUT * FIN) {
        float v = W[i];
        __nv_bfloat16 hi = __float2bfloat16(v);
        float r = v - __bfloat162float(hi);
        g_Wh[i] = hi;
        g_Wl[i] = __float2bfloat16(r);
    }
}

// ---------------- CSR build (edge indices are int32 on the wire) ----------------
__global__ void zero_cnt_kernel() {
    int i = blockIdx.x * blockDim.x + threadIdx.x;
    if (i < NNODES) g_cnt[i] = 0;
}

__global__ void hist_kernel(const int* __restrict__ er) {
    int e = blockIdx.x * blockDim.x + threadIdx.x;
    if (e < NEDGES) {
        unsigned r = (unsigned)er[e];
        if (r < NNODES) atomicAdd(&g_cnt[r], 1);
    }
}

__global__ void scan_kernel() {
    __shared__ int sc[1024];
    int t = threadIdx.x;
    int running = 0;
    for (int base = 0; base < NNODES; base += 1024) {
        int v = (base + t < NNODES) ? g_cnt[base + t] : 0;
        sc[t] = v;
        __syncthreads();
        for (int off = 1; off < 1024; off <<= 1) {
            int x = (t >= off) ? sc[t - off] : 0;
            __syncthreads();
            sc[t] += x;
            __syncthreads();
        }
        int incl = sc[t];
        int excl = incl - v;
        if (base + t < NNODES) {
            g_rowptr[base + t] = running + excl;
            g_wofs[base + t]   = running + excl;
        }
        __syncthreads();
        running += sc[1023];
        __syncthreads();
    }
    if (t == 0) g_rowptr[NNODES] = running;
}

__global__ void scatter_kernel(const int* __restrict__ er,
                               const int* __restrict__ ec,
                               const float* __restrict__ ev) {
    int e = blockIdx.x * blockDim.x + threadIdx.x;
    if (e < NEDGES) {
        unsigned r = (unsigned)er[e];
        unsigned c = (unsigned)ec[e];
        if (r < NNODES && c < NNODES) {
            int p = atomicAdd(&g_wofs[r], 1);
            g_scol[p] = (int)c;
            g_sval[p] = ev[e];
        }
    }
}

// ---------------- GEMM: h = x @ W^T via bf16-split mma.sync ----------------
// Block: 256 threads (8 warps), 64 rows x 128 cols.
// Warp grid: 4 (m) x 2 (n). Per warp: 16 rows x 64 cols = 8 m16n8 tiles.
#define XPITCH 136   // padded bf16 row pitch (conflict-free)
#define WPITCH 136

#define MMA_BF16(d, A0, A1, A2, A3, B0, B1)                                   \
    asm volatile(                                                             \
        "mma.sync.aligned.m16n8k16.row.col.f32.bf16.bf16.f32 "                \
        "{%0,%1,%2,%3}, {%4,%5,%6,%7}, {%8,%9}, {%0,%1,%2,%3};"               \
        : "+f"(d[0]), "+f"(d[1]), "+f"(d[2]), "+f"(d[3])                      \
        : "r"(A0), "r"(A1), "r"(A2), "r"(A3), "r"(B0), "r"(B1))

__global__ void gemm_kernel(const float* __restrict__ x) {
    extern __shared__ char smem[];
    __nv_bfloat16* XH = (__nv_bfloat16*)smem;                       // 64*136
    __nv_bfloat16* XL = XH + 64 * XPITCH;
    __nv_bfloat16* WH = XL + 64 * XPITCH;                           // 128*136
    __nv_bfloat16* WL = WH + 128 * WPITCH;

    int t = threadIdx.x;
    int blockRow = blockIdx.x * 64;

    // stage x tile, converting fp32 -> (hi, lo) bf16
    {
        const float4* xg = (const float4*)(x + (size_t)blockRow * FIN);
        #pragma unroll
        for (int i = 0; i < 8; i++) {
            int f4 = i * 256 + t;          // 0..2047
            int row = f4 >> 5;
            int c4  = (f4 & 31) * 4;
            float4 v = xg[(size_t)row * 32 + (c4 >> 2)];
            float vv[4] = {v.x, v.y, v.z, v.w};
            #pragma unroll
            for (int j = 0; j < 4; j++) {
                __nv_bfloat16 hi = __float2bfloat16(vv[j]);
                float r = vv[j] - __bfloat162float(hi);
                XH[row * XPITCH + c4 + j] = hi;
                XL[row * XPITCH + c4 + j] = __float2bfloat16(r);
            }
        }
    }
    // stage W (hi/lo) as u32 copies
    {
        const unsigned* whs = (const unsigned*)g_Wh;
        const unsigned* wls = (const unsigned*)g_Wl;
        #pragma unroll
        for (int i = 0; i < 32; i++) {
            int idx = i * 256 + t;         // 0..8191 u32
            int o  = idx >> 6;
            int k2 = (idx & 63) * 2;
            *(unsigned*)&WH[o * WPITCH + k2] = whs[idx];
            *(unsigned*)&WL[o * WPITCH + k2] = wls[idx];
        }
    }
    __syncthreads();

    int wid = t >> 5, lane = t & 31;
    int warp_m = wid >> 1, warp_n = wid & 1;
    int g  = lane >> 2;      // group id
    int tg = lane & 3;       // thread in group

    float acc[8][4];
    #pragma unroll
    for (int nt = 0; nt < 8; nt++)
        #pragma unroll
        for (int j = 0; j < 4; j++) acc[nt][j] = 0.f;

    int rowA = warp_m * 16 + g;

    #pragma unroll
    for (int ks = 0; ks < 8; ks++) {
        int k0 = ks * 16;
        unsigned ah0 = *(const unsigned*)&XH[rowA * XPITCH + k0 + 2 * tg];
        unsigned ah1 = *(const unsigned*)&XH[(rowA + 8) * XPITCH + k0 + 2 * tg];
        unsigned ah2 = *(const unsigned*)&XH[rowA * XPITCH + k0 + 8 + 2 * tg];
        unsigned ah3 = *(const unsigned*)&XH[(rowA + 8) * XPITCH + k0 + 8 + 2 * tg];
        unsigned al0 = *(const unsigned*)&XL[rowA * XPITCH + k0 + 2 * tg];
        unsigned al1 = *(const unsigned*)&XL[(rowA + 8) * XPITCH + k0 + 2 * tg];
        unsigned al2 = *(const unsigned*)&XL[rowA * XPITCH + k0 + 8 + 2 * tg];
        unsigned al3 = *(const unsigned*)&XL[(rowA + 8) * XPITCH + k0 + 8 + 2 * tg];

        #pragma unroll
        for (int nt = 0; nt < 8; nt++) {
            int o = warp_n * 64 + nt * 8 + g;
            unsigned bh0 = *(const unsigned*)&WH[o * WPITCH + k0 + 2 * tg];
            unsigned bh1 = *(const unsigned*)&WH[o * WPITCH + k0 + 8 + 2 * tg];
            unsigned bl0 = *(const unsigned*)&WL[o * WPITCH + k0 + 2 * tg];
            unsigned bl1 = *(const unsigned*)&WL[o * WPITCH + k0 + 8 + 2 * tg];
            MMA_BF16(acc[nt], ah0, ah1, ah2, ah3, bh0, bh1);   // hi*hi
            MMA_BF16(acc[nt], ah0, ah1, ah2, ah3, bl0, bl1);   // hi*lo
            MMA_BF16(acc[nt], al0, al1, al2, al3, bh0, bh1);   // lo*hi
        }
    }

    // epilogue: write fp32 h
    int m0 = blockRow + warp_m * 16 + g;
    #pragma unroll
    for (int nt = 0; nt < 8; nt++) {
        int c0 = warp_n * 64 + nt * 8 + 2 * tg;
        float2 v0 = make_float2(acc[nt][0], acc[nt][1]);
        float2 v1 = make_float2(acc[nt][2], acc[nt][3]);
        *(float2*)&g_h[(size_t)m0 * FOUT + c0]       = v0;
        *(float2*)&g_h[(size_t)(m0 + 8) * FOUT + c0] = v1;
    }
}

// ---------------- SpMM: warp per row, all 4 batches, atomic-free ----------------
__global__ void spmm_kernel(float* __restrict__ out) {
    int wg = (blockIdx.x * blockDim.x + threadIdx.x) >> 5;
    if (wg >= NNODES) return;
    int lane = threadIdx.x & 31;
    int start = g_rowptr[wg];
    int end   = g_rowptr[wg + 1];
    int fb = lane * 4;

    float4 a0 = make_float4(0.f, 0.f, 0.f, 0.f);
    float4 a1 = a0, a2 = a0, a3 = a0;

    for (int base = start; base < end; base += 32) {
        int n = min(32, end - base);
        int   c_l = 0;
        float v_l = 0.f;
        if (base + lane < end) {
            c_l = g_scol[base + lane];
            v_l = g_sval[base + lane];
        }
        for (int i = 0; i < n; i++) {
            int   c = __shfl_sync(0xffffffffu, c_l, i);
            float v = __shfl_sync(0xffffffffu, v_l, i);
            const float* hp = g_h + (size_t)c * FOUT + fb;
            float4 h0 = *(const float4*)(hp);
            float4 h1 = *(const float4*)(hp + NBSTRIDE);
            float4 h2 = *(const float4*)(hp + 2 * NBSTRIDE);
            float4 h3 = *(const float4*)(hp + 3 * NBSTRIDE);
            a0.x += v * h0.x; a0.y += v * h0.y; a0.z += v * h0.z; a0.w += v * h0.w;
            a1.x += v * h1.x; a1.y += v * h1.y; a1.z += v * h1.z; a1.w += v * h1.w;
            a2.x += v * h2.x; a2.y += v * h2.y; a2.z += v * h2.z; a2.w += v * h2.w;
            a3.x += v * h3.x; a3.y += v * h3.y; a3.z += v * h3.z; a3.w += v * h3.w;
        }
    }
    float* op = out + (size_t)wg * FOUT + fb;
    *(float4*)(op)                = a0;
    *(float4*)(op + NBSTRIDE)     = a1;
    *(float4*)(op + 2 * NBSTRIDE) = a2;
    *(float4*)(op + 3 * NBSTRIDE) = a3;
}

// ---------------- launch ----------------
extern "C" void kernel_launch(void* const* d_in, const int* in_sizes, int n_in,
                              void* d_out, int out_size) {
    const float* x  = (const float*)d_in[0];
    const float* W  = (const float*)d_in[1];
    const int*   er = (const int*)d_in[2];
    const int*   ec = (const int*)d_in[3];
    const float* ev = (const float*)d_in[4];
    float* out = (float*)d_out;

    const int smem_bytes = (64 * XPITCH * 2 + 128 * WPITCH * 2) * (int)sizeof(__nv_bfloat16);
    cudaFuncSetAttribute(gemm_kernel, cudaFuncAttributeMaxDynamicSharedMemorySize, smem_bytes);

    wsplit_kernel<<<(FOUT * FIN + 255) / 256, 256>>>(W);
    zero_cnt_kernel<<<(NNODES + 255) / 256, 256>>>();
    hist_kernel<<<(NEDGES + 255) / 256, 256>>>(er);
    scan_kernel<<<1, 1024>>>();
    scatter_kernel<<<(NEDGES + 255) / 256, 256>>>(er, ec, ev);
    gemm_kernel<<<MROWS / 64, 256, smem_bytes>>>(x);
    spmm_kernel<<<(NNODES + 7) / 8, 256>>>(out);
}

// round 5
// speedup vs baseline: 1.2440x; 1.2440x over previous
#include <cuda_runtime.h>
#include <cuda_bf16.h>
#include <cstdint>

// Problem constants (fixed by the dataset)
#define BATCH   4
#define NNODES  50000
#define NEDGES  800000
#define FIN     128
#define FOUT    128
#define MROWS   (BATCH * NNODES)          // 200000 GEMM rows
#define NBSTRIDE ((size_t)NNODES * FOUT)  // per-batch stride in h/out

// ---------------- device scratch (no cudaMalloc allowed) ----------------
__device__ float          g_h[(size_t)BATCH * NNODES * FOUT]; // 102.4 MB
__device__ __nv_bfloat16  g_Wh[FOUT * FIN];
__device__ __nv_bfloat16  g_Wl[FOUT * FIN];
__device__ int            g_cnt[NNODES];
__device__ int            g_rowptr[NNODES + 1];
__device__ int            g_wofs[NNODES];
__device__ int            g_scol[NEDGES];
__device__ float          g_sval[NEDGES];

#define SCAN_ELEMS 1024
#define SCAN_NBLK  ((NNODES + SCAN_ELEMS - 1) / SCAN_ELEMS)   // 49
__device__ int g_bsum[SCAN_NBLK];
__device__ int g_bofs[SCAN_NBLK];

// ---------------- prep: W split (bf16 hi/lo pair) + zero counters ----------------
__global__ void prep_kernel(const float* __restrict__ W) {
    int i = blockIdx.x * blockDim.x + threadIdx.x;
    if (i < FOUT * FIN) {
        float v = W[i];
        __nv_bfloat16 hi = __float2bfloat16(v);
        float r = v - __bfloat162float(hi);
        g_Wh[i] = hi;
        g_Wl[i] = __float2bfloat16(r);
    }
    if (i < NNODES) g_cnt[i] = 0;
}

// ---------------- CSR build (edge indices are int32 on the wire) ----------------
__global__ void hist_kernel(const int* __restrict__ er) {
    int e = blockIdx.x * blockDim.x + threadIdx.x;
    if (e < NEDGES) {
        unsigned r = (unsigned)er[e];
        if (r < NNODES) atomicAdd(&g_cnt[r], 1);
    }
}

// Phase 1: each 256-thread block scans 1024 counts (4/thread) via warp shuffles.
__global__ void scan1_kernel() {
    __shared__ int warp_sums[8];
    int b = blockIdx.x, t = threadIdx.x;
    int base = b * SCAN_ELEMS + t * 4;
    int v[4];
    #pragma unroll
    for (int j = 0; j < 4; j++)
        v[j] = (base + j < NNODES) ? g_cnt[base + j] : 0;
    int s = v[0] + v[1] + v[2] + v[3];

    int lane = t & 31, wid = t >> 5;
    int incl = s;
    #pragma unroll
    for (int off = 1; off < 32; off <<= 1) {
        int y = __shfl_up_sync(0xffffffffu, incl, off);
        if (lane >= off) incl += y;
    }
    if (lane == 31) warp_sums[wid] = incl;
    __syncthreads();
    if (wid == 0) {
        int ws = (lane < 8) ? warp_sums[lane] : 0;
        #pragma unroll
        for (int off = 1; off < 8; off <<= 1) {
            int y = __shfl_up_sync(0xffffffffu, ws, off);
            if (lane >= off) ws += y;
        }
        if (lane < 8) warp_sums[lane] = ws;
    }
    __syncthreads();

    int excl = incl - s + (wid > 0 ? warp_sums[wid - 1] : 0);
    int run = excl;
    #pragma unroll
    for (int j = 0; j < 4; j++) {
        if (base + j < NNODES) g_rowptr[base + j] = run;
        run += v[j];
    }
    if (t == 255) g_bsum[b] = run;   // block total
}

// Phase 2: one warp scans the 49 block sums.
__global__ void scan2_kernel() {
    int lane = threadIdx.x;
    int run = 0;
    for (int base = 0; base < SCAN_NBLK; base += 32) {
        int v = (base + lane < SCAN_NBLK) ? g_bsum[base + lane] : 0;
        int incl = v;
        #pragma unroll
        for (int off = 1; off < 32; off <<= 1) {
            int y = __shfl_up_sync(0xffffffffu, incl, off);
            if (lane >= off) incl += y;
        }
        if (base + lane < SCAN_NBLK) g_bofs[base + lane] = run + incl - v;
        run += __shfl_sync(0xffffffffu, incl, 31);
    }
    if (lane == 0) g_rowptr[NNODES] = run;
}

// Phase 3: add block offsets; also seed the scatter write cursors.
__global__ void scan3_kernel() {
    int i = blockIdx.x * blockDim.x + threadIdx.x;
    if (i < NNODES) {
        int p = g_rowptr[i] + g_bofs[i >> 10];
        g_rowptr[i] = p;
        g_wofs[i]   = p;
    }
}

__global__ void scatter_kernel(const int* __restrict__ er,
                               const int* __restrict__ ec,
                               const float* __restrict__ ev) {
    int e = blockIdx.x * blockDim.x + threadIdx.x;
    if (e < NEDGES) {
        unsigned r = (unsigned)er[e];
        unsigned c = (unsigned)ec[e];
        if (r < NNODES && c < NNODES) {
            int p = atomicAdd(&g_wofs[r], 1);
            g_scol[p] = (int)c;
            g_sval[p] = ev[e];
        }
    }
}

// ---------------- GEMM: h = x @ W^T via bf16-split mma.sync ----------------
// Block: 256 threads (8 warps), 64 rows x 128 cols.
// Warp grid: 4 (m) x 2 (n). Per warp: 16 rows x 64 cols = 8 m16n8 tiles.
#define XPITCH 136   // padded bf16 row pitch (conflict-free)
#define WPITCH 136

#define MMA_BF16(d, A0, A1, A2, A3, B0, B1)                                   \
    asm volatile(                                                             \
        "mma.sync.aligned.m16n8k16.row.col.f32.bf16.bf16.f32 "                \
        "{%0,%1,%2,%3}, {%4,%5,%6,%7}, {%8,%9}, {%0,%1,%2,%3};"               \
        : "+f"(d[0]), "+f"(d[1]), "+f"(d[2]), "+f"(d[3])                      \
        : "r"(A0), "r"(A1), "r"(A2), "r"(A3), "r"(B0), "r"(B1))

__global__ void gemm_kernel(const float* __restrict__ x) {
    extern __shared__ char smem[];
    __nv_bfloat16* XH = (__nv_bfloat16*)smem;                       // 64*136
    __nv_bfloat16* XL = XH + 64 * XPITCH;
    __nv_bfloat16* WH = XL + 64 * XPITCH;                           // 128*136
    __nv_bfloat16* WL = WH + 128 * WPITCH;

    int t = threadIdx.x;
    int blockRow = blockIdx.x * 64;

    // stage x tile, converting fp32 -> (hi, lo) bf16
    {
        const float4* xg = (const float4*)(x + (size_t)blockRow * FIN);
        #pragma unroll
        for (int i = 0; i < 8; i++) {
            int f4 = i * 256 + t;          // 0..2047
            int row = f4 >> 5;
            int c4  = (f4 & 31) * 4;
            float4 v = xg[(size_t)row * 32 + (c4 >> 2)];
            float vv[4] = {v.x, v.y, v.z, v.w};
            #pragma unroll
            for (int j = 0; j < 4; j++) {
                __nv_bfloat16 hi = __float2bfloat16(vv[j]);
                float r = vv[j] - __bfloat162float(hi);
                XH[row * XPITCH + c4 + j] = hi;
                XL[row * XPITCH + c4 + j] = __float2bfloat16(r);
            }
        }
    }
    // stage W (hi/lo) as u32 copies
    {
        const unsigned* whs = (const unsigned*)g_Wh;
        const unsigned* wls = (const unsigned*)g_Wl;
        #pragma unroll
        for (int i = 0; i < 32; i++) {
            int idx = i * 256 + t;         // 0..8191 u32
            int o  = idx >> 6;
            int k2 = (idx & 63) * 2;
            *(unsigned*)&WH[o * WPITCH + k2] = whs[idx];
            *(unsigned*)&WL[o * WPITCH + k2] = wls[idx];
        }
    }
    __syncthreads();

    int wid = t >> 5, lane = t & 31;
    int warp_m = wid >> 1, warp_n = wid & 1;
    int g  = lane >> 2;      // group id
    int tg = lane & 3;       // thread in group

    float acc[8][4];
    #pragma unroll
    for (int nt = 0; nt < 8; nt++)
        #pragma unroll
        for (int j = 0; j < 4; j++) acc[nt][j] = 0.f;

    int rowA = warp_m * 16 + g;

    #pragma unroll
    for (int ks = 0; ks < 8; ks++) {
        int k0 = ks * 16;
        unsigned ah0 = *(const unsigned*)&XH[rowA * XPITCH + k0 + 2 * tg];
        unsigned ah1 = *(const unsigned*)&XH[(rowA + 8) * XPITCH + k0 + 2 * tg];
        unsigned ah2 = *(const unsigned*)&XH[rowA * XPITCH + k0 + 8 + 2 * tg];
        unsigned ah3 = *(const unsigned*)&XH[(rowA + 8) * XPITCH + k0 + 8 + 2 * tg];
        unsigned al0 = *(const unsigned*)&XL[rowA * XPITCH + k0 + 2 * tg];
        unsigned al1 = *(const unsigned*)&XL[(rowA + 8) * XPITCH + k0 + 2 * tg];
        unsigned al2 = *(const unsigned*)&XL[rowA * XPITCH + k0 + 8 + 2 * tg];
        unsigned al3 = *(const unsigned*)&XL[(rowA + 8) * XPITCH + k0 + 8 + 2 * tg];

        #pragma unroll
        for (int nt = 0; nt < 8; nt++) {
            int o = warp_n * 64 + nt * 8 + g;
            unsigned bh0 = *(const unsigned*)&WH[o * WPITCH + k0 + 2 * tg];
            unsigned bh1 = *(const unsigned*)&WH[o * WPITCH + k0 + 8 + 2 * tg];
            unsigned bl0 = *(const unsigned*)&WL[o * WPITCH + k0 + 2 * tg];
            unsigned bl1 = *(const unsigned*)&WL[o * WPITCH + k0 + 8 + 2 * tg];
            MMA_BF16(acc[nt], ah0, ah1, ah2, ah3, bh0, bh1);   // hi*hi
            MMA_BF16(acc[nt], ah0, ah1, ah2, ah3, bl0, bl1);   // hi*lo
            MMA_BF16(acc[nt], al0, al1, al2, al3, bh0, bh1);   // lo*hi
        }
    }

    // epilogue: write fp32 h
    int m0 = blockRow + warp_m * 16 + g;
    #pragma unroll
    for (int nt = 0; nt < 8; nt++) {
        int c0 = warp_n * 64 + nt * 8 + 2 * tg;
        float2 v0 = make_float2(acc[nt][0], acc[nt][1]);
        float2 v1 = make_float2(acc[nt][2], acc[nt][3]);
        *(float2*)&g_h[(size_t)m0 * FOUT + c0]       = v0;
        *(float2*)&g_h[(size_t)(m0 + 8) * FOUT + c0] = v1;
    }
}

// ---------------- SpMM: warp per row, all 4 batches, atomic-free ----------------
__global__ void spmm_kernel(float* __restrict__ out) {
    int wg = (blockIdx.x * blockDim.x + threadIdx.x) >> 5;
    if (wg >= NNODES) return;
    int lane = threadIdx.x & 31;
    int start = g_rowptr[wg];
    int end   = g_rowptr[wg + 1];
    int fb = lane * 4;

    float4 a0 = make_float4(0.f, 0.f, 0.f, 0.f);
    float4 a1 = a0, a2 = a0, a3 = a0;

    for (int base = start; base < end; base += 32) {
        int n = min(32, end - base);
        int   c_l = 0;
        float v_l = 0.f;
        if (base + lane < end) {
            c_l = g_scol[base + lane];
            v_l = g_sval[base + lane];
        }
        for (int i = 0; i < n; i++) {
            int   c = __shfl_sync(0xffffffffu, c_l, i);
            float v = __shfl_sync(0xffffffffu, v_l, i);
            const float* hp = g_h + (size_t)c * FOUT + fb;
            float4 h0 = *(const float4*)(hp);
            float4 h1 = *(const float4*)(hp + NBSTRIDE);
            float4 h2 = *(const float4*)(hp + 2 * NBSTRIDE);
            float4 h3 = *(const float4*)(hp + 3 * NBSTRIDE);
            a0.x += v * h0.x; a0.y += v * h0.y; a0.z += v * h0.z; a0.w += v * h0.w;
            a1.x += v * h1.x; a1.y += v * h1.y; a1.z += v * h1.z; a1.w += v * h1.w;
            a2.x += v * h2.x; a2.y += v * h2.y; a2.z += v * h2.z; a2.w += v * h2.w;
            a3.x += v * h3.x; a3.y += v * h3.y; a3.z += v * h3.z; a3.w += v * h3.w;
        }
    }
    float* op = out + (size_t)wg * FOUT + fb;
    *(float4*)(op)                = a0;
    *(float4*)(op + NBSTRIDE)     = a1;
    *(float4*)(op + 2 * NBSTRIDE) = a2;
    *(float4*)(op + 3 * NBSTRIDE) = a3;
}

// ---------------- launch ----------------
extern "C" void kernel_launch(void* const* d_in, const int* in_sizes, int n_in,
                              void* d_out, int out_size) {
    const float* x  = (const float*)d_in[0];
    const float* W  = (const float*)d_in[1];
    const int*   er = (const int*)d_in[2];
    const int*   ec = (const int*)d_in[3];
    const float* ev = (const float*)d_in[4];
    float* out = (float*)d_out;

    const int smem_bytes = (64 * XPITCH * 2 + 128 * WPITCH * 2) * (int)sizeof(__nv_bfloat16);
    cudaFuncSetAttribute(gemm_kernel, cudaFuncAttributeMaxDynamicSharedMemorySize, smem_bytes);

    prep_kernel<<<(NNODES + 255) / 256, 256>>>(W);
    hist_kernel<<<(NEDGES + 255) / 256, 256>>>(er);
    scan1_kernel<<<SCAN_NBLK, 256>>>();
    scan2_kernel<<<1, 32>>>();
    scan3_kernel<<<(NNODES + 255) / 256, 256>>>();
    scatter_kernel<<<(NEDGES + 255) / 256, 256>>>(er, ec, ev);
    gemm_kernel<<<MROWS / 64, 256, smem_bytes>>>(x);
    spmm_kernel<<<(NNODES + 7) / 8, 256>>>(out);
}